// round 15
// baseline (speedup 1.0000x reference)
#include <cuda_runtime.h>
#include <cuda_bf16.h>
#include <cstdint>

#define HID     32
#define TILE_M  128                  // 8 warps x 16 rows, disjoint
#define THREADS 256
#define BSTRIDE 136                  // padded bf16 per B row (272B): conflict-free ldmatrix
#define BHALF   (64 * BSTRIDE)       // elements per version (hi/lo)

#define APITCH   80                  // bytes per A row: bank-permutation, 16B-aligned
#define ASTAGE   (16 * APITCH)       // 1280 B per stage per warp
#define ADEPTH   3
#define ARING    (8 * ADEPTH * ASTAGE)       // 30720 B
#define SB_OFF   ARING
#define SMEM_DYN (ARING + 2 * BHALF * 2)     // + 34816 B = 65536

// ---------------- helpers ----------------
__device__ __forceinline__ uint32_t smem_u32(const void* p) {
    uint32_t a;
    asm("{ .reg .u64 t; cvta.to.shared.u64 t, %1; cvt.u32.u64 %0, t; }" : "=r"(a) : "l"(p));
    return a;
}
__device__ __forceinline__ void mma_bf16(float* d, const uint32_t* a, const uint32_t* b) {
    asm volatile(
        "mma.sync.aligned.m16n8k16.row.col.f32.bf16.bf16.f32 "
        "{%0,%1,%2,%3}, {%4,%5,%6,%7}, {%8,%9}, {%0,%1,%2,%3};"
        : "+f"(d[0]), "+f"(d[1]), "+f"(d[2]), "+f"(d[3])
        : "r"(a[0]), "r"(a[1]), "r"(a[2]), "r"(a[3]), "r"(b[0]), "r"(b[1]));
}
__device__ __forceinline__ void ldm_x4(uint32_t* r, uint32_t addr) {
    asm volatile("ldmatrix.sync.aligned.m8n8.x4.shared.b16 {%0,%1,%2,%3}, [%4];"
        : "=r"(r[0]), "=r"(r[1]), "=r"(r[2]), "=r"(r[3]) : "r"(addr));
}
__device__ __forceinline__ void cpasync16(uint32_t dst, const void* src) {
    asm volatile("cp.async.cg.shared.global [%0], [%1], 16;" :: "r"(dst), "l"(src));
}
__device__ __forceinline__ void cp_commit() {
    asm volatile("cp.async.commit_group;" ::: "memory");
}
__device__ __forceinline__ void cp_wait2() {
    asm volatile("cp.async.wait_group 2;" ::: "memory");
}
__device__ __forceinline__ uint32_t pack_bf2(float a, float b) {
    __nv_bfloat162 t = __floats2bfloat162_rn(a, b);
    return *(uint32_t*)&t;
}
__device__ __forceinline__ float sigmoid_f(float v) {
    return __fdividef(1.0f, 1.0f + __expf(-v));
}
__device__ __forceinline__ float tanh_f(float v) {
    return 1.0f - __fdividef(2.0f, __expf(2.0f * v) + 1.0f);
}

__global__ void __launch_bounds__(THREADS, 3)
dcrnn_mma_kernel(const float* __restrict__ x,
                 const float* __restrict__ Wz, const float* __restrict__ Wh,
                 const float* __restrict__ bz, const float* __restrict__ bh,
                 const float* __restrict__ wlin, const float* __restrict__ blin,
                 float* __restrict__ out, int nNodes)
{
    extern __shared__ __align__(16) unsigned char dsm[];
    unsigned char* smA = dsm;                 // A ring: warp w stage s at (w*ADEPTH+s)*ASTAGE
    __nv_bfloat16*  sB = (__nv_bfloat16*)(dsm + SB_OFF);

    const int tid = threadIdx.x;
    const int warp = tid >> 5;
    const int lane = tid & 31;
    const int g    = lane >> 2;        // 0..7
    const int c    = lane & 3;         // 0..3
    const int r8   = lane >> 2;        // async row-in-octet
    const int ch   = lane & 3;         // async 16B chunk
    const int rowBase = blockIdx.x * TILE_M + warp * 16;

    const uint32_t warpRing = smem_u32(smA) + (uint32_t)(warp * ADEPTH * ASTAGE);

    // ---- async producer: stage 'st' <- 16 A rows for k-tile kt (2 cp.async/lane) ----
    auto issueA = [&](int kt, int st) {
        uint32_t dstBase = warpRing + (uint32_t)(st * ASTAGE);
        #pragma unroll
        for (int j = 0; j < 2; j++) {
            int lrow = j * 8 + r8;
            int grow = rowBase + lrow;
            if (grow >= nNodes) grow = nNodes - 1;
            const void* src = x + (size_t)grow * 128 + kt * 16 + ch * 4;
            cpasync16(dstBase + (uint32_t)(lrow * APITCH + ch * 16), src);
        }
    };

    // prologue: stages 0,1,2 <- kt 0,1,2 (DRAM traffic in flight during B prep below)
    issueA(0, 0); cp_commit();
    issueA(1, 1); cp_commit();
    issueA(2, 2); cp_commit();

    // ---- fused B prep: build split-bf16 W^T tiles directly from W_z/W_h ----
    // W tensors shape (2,1,160,32); [s,0,k,j] = s*5120 + k*32 + j; only k<128 live (H0=0).
    // sB row n (n<32: z col n, n>=32: h col n-32), col k. Coalesced: thread lane = j.
    {
        const int j  = tid & 31;              // gate column (coalesced across lanes)
        const int k0 = (tid >> 5) * 16;       // 16-k slab per warp
        #pragma unroll
        for (int kk = 0; kk < 16; kk++) {
            int k = k0 + kk;
            float vz = Wz[k * 32 + j] + Wz[5120 + k * 32 + j];
            float vh = Wh[k * 32 + j] + Wh[5120 + k * 32 + j];
            __nv_bfloat16 zh = __float2bfloat16_rn(vz);
            __nv_bfloat16 hh = __float2bfloat16_rn(vh);
            sB[j * BSTRIDE + k]                  = zh;
            sB[(j + 32) * BSTRIDE + k]           = hh;
            sB[BHALF + j * BSTRIDE + k]          = __float2bfloat16_rn(vz - __bfloat162float(zh));
            sB[BHALF + (j + 32) * BSTRIDE + k]   = __float2bfloat16_rn(vh - __bfloat162float(hh));
        }
    }
    __syncthreads();

    // B ldmatrix per-thread address component:
    const uint32_t sB0 = smem_u32(sB);
    const uint32_t tb  = (uint32_t)((((lane >> 4) << 3) + (lane & 7)) * (BSTRIDE * 2)
                                    + ((lane >> 3) & 1) * 16);
    const uint32_t bbase = sB0 + tb;

    float acc[8][4];
    #pragma unroll
    for (int nt = 0; nt < 8; nt++)
        #pragma unroll
        for (int e = 0; e < 4; e++) acc[nt][e] = 0.0f;

    #pragma unroll
    for (int kt = 0; kt < 8; kt++) {
        const int scur = kt % ADEPTH;

        cp_wait2();              // group kt complete (<=2 pending)
        __syncwarp();

        // consume stage scur: fragment LDS.64 (bank-permutation pitch) + hi/lo split
        unsigned char* stp = smA + warp * ADEPTH * ASTAGE + scur * ASTAGE;
        uint32_t Ah[4], Al[4];
        {
            int r0 = g;
            int r1 = g + 8;
            float2 f0 = *(const float2*)(stp + r0 * APITCH + 8 * c);        // cols 2c,2c+1
            float2 f1 = *(const float2*)(stp + r1 * APITCH + 8 * c);
            float2 f2 = *(const float2*)(stp + r0 * APITCH + 32 + 8 * c);   // cols 8+2c
            float2 f3 = *(const float2*)(stp + r1 * APITCH + 32 + 8 * c);
            float2 fv[4] = {f0, f1, f2, f3};
            #pragma unroll
            for (int q = 0; q < 4; q++) {
                __nv_bfloat162 h2 = __floats2bfloat162_rn(fv[q].x, fv[q].y);
                float lx = fv[q].x - __bfloat162float(h2.x);
                float ly = fv[q].y - __bfloat162float(h2.y);
                Ah[q] = *(uint32_t*)&h2;
                Al[q] = pack_bf2(lx, ly);
            }
        }

        // refill: stage scur <- kt+3
        if (kt + 3 < 8) issueA(kt + 3, scur);
        cp_commit();             // uniform group counting

        // B fragments interleaved per n-pair: hi+lo issued together, 6 MMAs per pair.
        #pragma unroll
        for (int q = 0; q < 4; q++) {
            uint32_t Bhi[4], Blo[4];
            ldm_x4(Bhi, bbase + q * (16 * BSTRIDE * 2) + kt * 32);
            ldm_x4(Blo, bbase + 2 * BHALF + q * (16 * BSTRIDE * 2) + kt * 32);
            mma_bf16(acc[2 * q + 0], Ah, Bhi + 0);   // xh * wh
            mma_bf16(acc[2 * q + 0], Al, Bhi + 0);   // xl * wh
            mma_bf16(acc[2 * q + 0], Ah, Blo + 0);   // xh * wl
            mma_bf16(acc[2 * q + 1], Ah, Bhi + 2);
            mma_bf16(acc[2 * q + 1], Al, Bhi + 2);
            mma_bf16(acc[2 * q + 1], Ah, Blo + 2);
        }
    }

    // ---- epilogue: z at col j (n-tiles 0..3), h at col j+32 (n-tiles 4..7),
    //      both owned by the same thread. Quad shfl-reduce, lane c==0 stores.
    float bl = __ldg(blin);
    #pragma unroll
    for (int r = 0; r < 2; r++) {
        int eb = r * 2;                // c0/c1 = row g, c2/c3 = row g+8
        float partial = 0.0f;
        #pragma unroll
        for (int ntz = 0; ntz < 4; ntz++) {
            #pragma unroll
            for (int e = 0; e < 2; e++) {
                int j = ntz * 8 + 2 * c + e;
                float zv = acc[ntz][eb + e]     + __ldg(bz + j);
                float hv = acc[ntz + 4][eb + e] + __ldg(bh + j);
                float zz = sigmoid_f(zv);
                float ht = tanh_f(hv);
                partial = fmaf(fmaxf((1.0f - zz) * ht, 0.0f), __ldg(wlin + j), partial);
            }
        }
        partial += __shfl_xor_sync(0xffffffffu, partial, 1);
        partial += __shfl_xor_sync(0xffffffffu, partial, 2);
        if (c == 0) {
            int grow = rowBase + g + 8 * r;
            if (grow < nNodes) out[grow] = partial + bl;
        }
    }
}

// Inputs (metadata order):
// 0:x[N*128] f32   1:edge_index (dead)   2:edge_weight (dead)
// 3:W_z[10240]     4:b_z[32]   5:W_r (dead)   6:b_r (dead)
// 7:W_h[10240]     8:b_h[32]   9:W_lin[32]   10:b_lin[1]
extern "C" void kernel_launch(void* const* d_in, const int* in_sizes, int n_in,
                              void* d_out, int out_size) {
    const float* x     = (const float*)d_in[0];
    const float* W_z   = (const float*)d_in[3];
    const float* b_z   = (const float*)d_in[4];
    const float* W_h   = (const float*)d_in[7];
    const float* b_h   = (const float*)d_in[8];
    const float* W_lin = (const float*)d_in[9];
    const float* b_lin = (const float*)d_in[10];
    float* out = (float*)d_out;

    int nNodes = out_size;

    // Idempotent, every call (no static guards per harness rules)
    cudaFuncSetAttribute(dcrnn_mma_kernel,
                         cudaFuncAttributeMaxDynamicSharedMemorySize, SMEM_DYN);

    int blocks = (nNodes + TILE_M - 1) / TILE_M;
    dcrnn_mma_kernel<<<blocks, THREADS, SMEM_DYN>>>(x, W_z, W_h, b_z, b_h,
                                                    W_lin, b_lin, out, nNodes);
}

// round 16
// speedup vs baseline: 1.0771x; 1.0771x over previous
#include <cuda_runtime.h>
#include <cuda_bf16.h>
#include <cstdint>

#define HID     32
#define TILE_M  256
#define THREADS 256

#define APITCH   80                  // bytes per A row: bank-permutation, 16B-aligned
#define ASTAGE   (32 * APITCH)       // 2560 B per stage per warp
#define ADEPTH   3
#define ARING    (8 * ADEPTH * ASTAGE)       // 61440 B
#define SBF_OFF  ARING
#define SBF_BYTES (8 * 2 * 8 * 32 * 8)       // [kt][step][q][lane] x uint2 = 32768 B
#define SMEM_DYN (ARING + SBF_BYTES)         // 94208

// ---------------- helpers ----------------
__device__ __forceinline__ uint32_t smem_u32(const void* p) {
    uint32_t a;
    asm("{ .reg .u64 t; cvta.to.shared.u64 t, %1; cvt.u32.u64 %0, t; }" : "=r"(a) : "l"(p));
    return a;
}
__device__ __forceinline__ uint32_t f2tf32(float f) {
    uint32_t r;
    asm("cvt.rna.tf32.f32 %0, %1;" : "=r"(r) : "f"(f));
    return r;
}
__device__ __forceinline__ void mma_tf32(float* d, const uint32_t* a, uint32_t b0, uint32_t b1) {
    asm volatile(
        "mma.sync.aligned.m16n8k8.row.col.f32.tf32.tf32.f32 "
        "{%0,%1,%2,%3}, {%4,%5,%6,%7}, {%8,%9}, {%0,%1,%2,%3};"
        : "+f"(d[0]), "+f"(d[1]), "+f"(d[2]), "+f"(d[3])
        : "r"(a[0]), "r"(a[1]), "r"(a[2]), "r"(a[3]), "r"(b0), "r"(b1));
}
__device__ __forceinline__ void cpasync16(uint32_t dst, const void* src) {
    asm volatile("cp.async.cg.shared.global [%0], [%1], 16;" :: "r"(dst), "l"(src));
}
__device__ __forceinline__ void cp_commit() {
    asm volatile("cp.async.commit_group;" ::: "memory");
}
__device__ __forceinline__ void cp_wait2() {
    asm volatile("cp.async.wait_group 2;" ::: "memory");
}
__device__ __forceinline__ float sigmoid_f(float v) {
    return __fdividef(1.0f, 1.0f + __expf(-v));
}
__device__ __forceinline__ float tanh_f(float v) {
    return 1.0f - __fdividef(2.0f, __expf(2.0f * v) + 1.0f);
}

__global__ void __launch_bounds__(THREADS, 2)
dcrnn_mma_kernel(const float* __restrict__ x,
                 const float* __restrict__ Wz, const float* __restrict__ Wh,
                 const float* __restrict__ bz, const float* __restrict__ bh,
                 const float* __restrict__ wlin, const float* __restrict__ blin,
                 float* __restrict__ out, int nNodes)
{
    extern __shared__ __align__(16) unsigned char dsm[];
    unsigned char* smA = dsm;                 // A ring: warp w stage s at (w*ADEPTH+s)*ASTAGE
    uint2* sBf = (uint2*)(dsm + SBF_OFF);     // B fragments, pre-converted tf32

    const int tid = threadIdx.x;
    const int warp = tid >> 5;
    const int lane = tid & 31;
    const int g    = lane >> 2;        // 0..7
    const int c    = lane & 3;         // 0..3
    const int r8   = lane >> 2;        // async row-in-octet
    const int ch   = lane & 3;         // async 16B chunk
    const int rowBase = blockIdx.x * TILE_M + warp * 32;

    const uint32_t warpRing = smem_u32(smA) + (uint32_t)(warp * ADEPTH * ASTAGE);

    // ---- async producer: stage 'st' <- 32 A rows for k-tile kt ----
    auto issueA = [&](int kt, int st) {
        uint32_t dstBase = warpRing + (uint32_t)(st * ASTAGE);
        #pragma unroll
        for (int j = 0; j < 4; j++) {
            int lrow = j * 8 + r8;
            int grow = rowBase + lrow;
            if (grow >= nNodes) grow = nNodes - 1;
            const void* src = x + (size_t)grow * 128 + kt * 16 + ch * 4;
            cpasync16(dstBase + (uint32_t)(lrow * APITCH + ch * 16), src);
        }
    };

    // prologue: stages 0,1,2 <- kt 0,1,2 (DRAM traffic in flight during B prep below)
    issueA(0, 0); cp_commit();
    issueA(1, 1); cp_commit();
    issueA(2, 2); cp_commit();

    // ---- fused B prep: fragment-major pre-converted tf32 W^T ----
    // W tensors shape (2,1,160,32); [s,0,k,j] = s*5120 + k*32 + j; only k<128 live (H0=0).
    // Entry e = (((kt*2+s)*8+q)*32+lane): lane=(g',c) holds b0=W[k0][n], b1=W[k0+4][n]
    // with k0 = kt*16+s*8+c, n = q*8+g' (n<32: z col n, n>=32: h col n-32).
    {
        #pragma unroll
        for (int i = 0; i < 16; i++) {
            int e   = tid + i * THREADS;       // 0..4095
            int le  = e & 31;
            int q   = (e >> 5) & 7;
            int s   = (e >> 8) & 1;
            int kt  = e >> 9;
            int gp  = le >> 2;
            int cc  = le & 3;
            int n   = q * 8 + gp;
            int j   = n & 31;
            int k0  = kt * 16 + s * 8 + cc;
            const float* W = (n < 32) ? Wz : Wh;
            float v0 = W[k0 * 32 + j]       + W[5120 + k0 * 32 + j];
            float v1 = W[(k0 + 4) * 32 + j] + W[5120 + (k0 + 4) * 32 + j];
            sBf[e] = make_uint2(f2tf32(v0), f2tf32(v1));
        }
    }
    __syncthreads();

    float acc[2][8][4];
    #pragma unroll
    for (int mt = 0; mt < 2; mt++)
        #pragma unroll
        for (int nt = 0; nt < 8; nt++)
            #pragma unroll
            for (int e = 0; e < 4; e++) acc[mt][nt][e] = 0.0f;

    #pragma unroll
    for (int kt = 0; kt < 8; kt++) {
        const int scur = kt % ADEPTH;

        cp_wait2();              // group kt complete (<=2 pending)
        __syncwarp();

        // consume stage scur: per (s, mt) fragment = 4x LDS.32 (bank-permutation
        // (20*row + col) % 32 is conflict-free) + cvt.rna to tf32
        unsigned char* stp = smA + warp * ADEPTH * ASTAGE + scur * ASTAGE;
        uint32_t At[2][2][4];    // [s][mt][frag]
        #pragma unroll
        for (int s = 0; s < 2; s++) {
            #pragma unroll
            for (int mt = 0; mt < 2; mt++) {
                int r0 = g + 16 * mt;
                int r1 = r0 + 8;
                int col0 = s * 8 + c;
                float a0 = *(const float*)(stp + r0 * APITCH + col0 * 4);
                float a1 = *(const float*)(stp + r1 * APITCH + col0 * 4);
                float a2 = *(const float*)(stp + r0 * APITCH + (col0 + 4) * 4);
                float a3 = *(const float*)(stp + r1 * APITCH + (col0 + 4) * 4);
                At[s][mt][0] = f2tf32(a0);
                At[s][mt][1] = f2tf32(a1);
                At[s][mt][2] = f2tf32(a2);
                At[s][mt][3] = f2tf32(a3);
            }
        }

        // refill: stage scur <- kt+3
        if (kt + 3 < 8) issueA(kt + 3, scur);
        cp_commit();             // uniform group counting

        // MMA: 2 k8-steps x 8 n-tiles x 2 m-tiles, B via lane-strided LDS.64
        #pragma unroll
        for (int s = 0; s < 2; s++) {
            #pragma unroll
            for (int q = 0; q < 8; q++) {
                uint2 b = sBf[(((kt * 2 + s) * 8 + q) * 32) + lane];
                mma_tf32(acc[0][q], At[s][0], b.x, b.y);
                mma_tf32(acc[1][q], At[s][1], b.x, b.y);
            }
        }
    }

    // ---- epilogue: z at col j (n-tiles 0..3), h at col j+32 (n-tiles 4..7),
    //      both owned by the same thread. Quad shfl-reduce, lane c==0 stores.
    float bl = __ldg(blin);
    #pragma unroll
    for (int r = 0; r < 4; r++) {
        int mt = r >> 1;
        int eb = (r & 1) * 2;          // c0/c1 = row g, c2/c3 = row g+8
        float partial = 0.0f;
        #pragma unroll
        for (int ntz = 0; ntz < 4; ntz++) {
            #pragma unroll
            for (int e = 0; e < 2; e++) {
                int j = ntz * 8 + 2 * c + e;
                float zv = acc[mt][ntz][eb + e]     + __ldg(bz + j);
                float hv = acc[mt][ntz + 4][eb + e] + __ldg(bh + j);
                float zz = sigmoid_f(zv);
                float ht = tanh_f(hv);
                partial = fmaf(fmaxf((1.0f - zz) * ht, 0.0f), __ldg(wlin + j), partial);
            }
        }
        partial += __shfl_xor_sync(0xffffffffu, partial, 1);
        partial += __shfl_xor_sync(0xffffffffu, partial, 2);
        if (c == 0) {
            int grow = rowBase + g + 8 * r;
            if (grow < nNodes) out[grow] = partial + bl;
        }
    }
}

// Inputs (metadata order):
// 0:x[N*128] f32   1:edge_index (dead)   2:edge_weight (dead)
// 3:W_z[10240]     4:b_z[32]   5:W_r (dead)   6:b_r (dead)
// 7:W_h[10240]     8:b_h[32]   9:W_lin[32]   10:b_lin[1]
extern "C" void kernel_launch(void* const* d_in, const int* in_sizes, int n_in,
                              void* d_out, int out_size) {
    const float* x     = (const float*)d_in[0];
    const float* W_z   = (const float*)d_in[3];
    const float* b_z   = (const float*)d_in[4];
    const float* W_h   = (const float*)d_in[7];
    const float* b_h   = (const float*)d_in[8];
    const float* W_lin = (const float*)d_in[9];
    const float* b_lin = (const float*)d_in[10];
    float* out = (float*)d_out;

    int nNodes = out_size;

    // Idempotent, every call (no static guards per harness rules)
    cudaFuncSetAttribute(dcrnn_mma_kernel,
                         cudaFuncAttributeMaxDynamicSharedMemorySize, SMEM_DYN);

    int blocks = (nNodes + TILE_M - 1) / TILE_M;
    dcrnn_mma_kernel<<<blocks, THREADS, SMEM_DYN>>>(x, W_z, W_h, b_z, b_h,
                                                    W_lin, b_lin, out, nNodes);
}